// round 10
// baseline (speedup 1.0000x reference)
#include <cuda_runtime.h>

// ISNE embedding gather + masked-mean.
// Inputs (metadata order):
//   d_in[0] node_parameters  float32 [1000000, 128]
//   d_in[1] node_indices     int32   [16384]
//   d_in[2] pos_idx          int32   [16384, 32]
//   d_in[3] pos_len          int32   [16384]
//   d_in[4] neg_idx          int32   [16384, 32]
//   d_in[5] neg_len          int32   [16384]
// Output: concat(node_embeds, pos_embeds, neg_embeds) float32 [3*16384*128]
//
// One warp per output row. Lane l owns float4 #l of the 128-float row.
// Neighbor indices live one-per-lane in a register and are shfl-broadcast.
//
// Software-pipelined mean loop (double-buffered 4-row batches):
//   prologue: load batch 0
//   steady:   issue loads for batch j, THEN accumulate batch j-1
// so the warp always has 4-8 LDG.128 outstanding — the shfl + FADD phases
// are covered by in-flight memory instead of going dark between batches.

#define FULL_MASK 0xFFFFFFFFu
static constexpr int D4 = 32;  // float4s per 128-float row
static constexpr int K  = 32;  // max neighbors

__global__ __launch_bounds__(256) void isne_gather_mean_kernel(
    const float4* __restrict__ table,
    const int*    __restrict__ node_idx,
    const int*    __restrict__ pos_idx,
    const int*    __restrict__ pos_len,
    const int*    __restrict__ neg_idx,
    const int*    __restrict__ neg_len,
    float4*       __restrict__ out,
    int B)
{
    const int gwarp = (int)((blockIdx.x * blockDim.x + threadIdx.x) >> 5);
    const int lane  = threadIdx.x & 31;
    if (gwarp >= 3 * B) return;

    int task, b;
    if (gwarp < B)            { task = 0; b = gwarp;         }
    else if (gwarp < 2 * B)   { task = 1; b = gwarp - B;     }
    else                      { task = 2; b = gwarp - 2 * B; }

    const float4* __restrict__ tab = table + lane;  // lane-offset base

    if (task == 0) {
        const int idx = __ldg(&node_idx[b]);
        out[(size_t)b * D4 + lane] = __ldg(&tab[(size_t)idx * D4]);
        return;
    }

    const int* __restrict__ idxs = (task == 1) ? pos_idx : neg_idx;
    const int* __restrict__ lens = (task == 1) ? pos_len : neg_len;

    const int len   = __ldg(&lens[b]);
    const int myidx = __ldg(&idxs[(size_t)b * K + lane]);  // lane k holds idx[k]

    float4 acc = make_float4(0.f, 0.f, 0.f, 0.f);

    const int nb = len >> 2;   // number of full 4-row batches
    int k = 0;

    if (nb > 0) {
        // ---- prologue: load batch 0 ----
        int i0 = __shfl_sync(FULL_MASK, myidx, 0);
        int i1 = __shfl_sync(FULL_MASK, myidx, 1);
        int i2 = __shfl_sync(FULL_MASK, myidx, 2);
        int i3 = __shfl_sync(FULL_MASK, myidx, 3);
        float4 p0 = __ldg(&tab[(size_t)i0 * D4]);
        float4 p1 = __ldg(&tab[(size_t)i1 * D4]);
        float4 p2 = __ldg(&tab[(size_t)i2 * D4]);
        float4 p3 = __ldg(&tab[(size_t)i3 * D4]);

        // ---- steady state: issue batch j, accumulate batch j-1 ----
        for (int j = 1; j < nb; ++j) {
            const int base = j << 2;
            const int j0 = __shfl_sync(FULL_MASK, myidx, base);
            const int j1 = __shfl_sync(FULL_MASK, myidx, base + 1);
            const int j2 = __shfl_sync(FULL_MASK, myidx, base + 2);
            const int j3 = __shfl_sync(FULL_MASK, myidx, base + 3);
            const float4 q0 = __ldg(&tab[(size_t)j0 * D4]);
            const float4 q1 = __ldg(&tab[(size_t)j1 * D4]);
            const float4 q2 = __ldg(&tab[(size_t)j2 * D4]);
            const float4 q3 = __ldg(&tab[(size_t)j3 * D4]);
            // accumulate the previous batch while q's are in flight
            acc.x += (p0.x + p1.x) + (p2.x + p3.x);
            acc.y += (p0.y + p1.y) + (p2.y + p3.y);
            acc.z += (p0.z + p1.z) + (p2.z + p3.z);
            acc.w += (p0.w + p1.w) + (p2.w + p3.w);
            p0 = q0; p1 = q1; p2 = q2; p3 = q3;
        }

        // ---- epilogue: accumulate the last in-flight batch ----
        acc.x += (p0.x + p1.x) + (p2.x + p3.x);
        acc.y += (p0.y + p1.y) + (p2.y + p3.y);
        acc.z += (p0.z + p1.z) + (p2.z + p3.z);
        acc.w += (p0.w + p1.w) + (p2.w + p3.w);

        k = nb << 2;
    }

    // ---- tail: 0-3 remaining rows, loads issued before accumulation ----
    {
        const int rem = len - k;
        if (rem > 0) {
            const int t0 = __shfl_sync(FULL_MASK, myidx, k);
            const int t1 = __shfl_sync(FULL_MASK, myidx, (rem > 1) ? k + 1 : k);
            const int t2 = __shfl_sync(FULL_MASK, myidx, (rem > 2) ? k + 2 : k);
            const float4 v0 = __ldg(&tab[(size_t)t0 * D4]);
            acc.x += v0.x; acc.y += v0.y; acc.z += v0.z; acc.w += v0.w;
            if (rem > 1) {
                const float4 v1 = __ldg(&tab[(size_t)t1 * D4]);
                acc.x += v1.x; acc.y += v1.y; acc.z += v1.z; acc.w += v1.w;
            }
            if (rem > 2) {
                const float4 v2 = __ldg(&tab[(size_t)t2 * D4]);
                acc.x += v2.x; acc.y += v2.y; acc.z += v2.z; acc.w += v2.w;
            }
        }
    }

    const float scale = (len > 0) ? (1.0f / (float)len) : 0.0f;
    acc.x *= scale; acc.y *= scale; acc.z *= scale; acc.w *= scale;

    out[((size_t)task * B + b) * D4 + lane] = acc;
}

extern "C" void kernel_launch(void* const* d_in, const int* in_sizes, int n_in,
                              void* d_out, int out_size)
{
    const float4* table = (const float4*)d_in[0];
    const int*    nidx  = (const int*)d_in[1];
    const int*    pidx  = (const int*)d_in[2];
    const int*    plen  = (const int*)d_in[3];
    const int*    gidx  = (const int*)d_in[4];
    const int*    glen  = (const int*)d_in[5];
    float4*       out   = (float4*)d_out;

    const int B = in_sizes[1];  // 16384

    const int total_threads = 3 * B * 32;  // one warp per output row
    const int threads = 256;
    const int blocks  = (total_threads + threads - 1) / threads;

    isne_gather_mean_kernel<<<blocks, threads>>>(
        table, nidx, pidx, plen, gidx, glen, out, B);
}

// round 13
// speedup vs baseline: 1.1045x; 1.1045x over previous
#include <cuda_runtime.h>
#include <cstdint>

// ISNE embedding gather + masked-mean — cp.async deep-pipeline version.
// Inputs (metadata order):
//   d_in[0] node_parameters  float32 [1000000, 128]
//   d_in[1] node_indices     int32   [16384]
//   d_in[2] pos_idx          int32   [16384, 32]
//   d_in[3] pos_len          int32   [16384]
//   d_in[4] neg_idx          int32   [16384, 32]
//   d_in[5] neg_len          int32   [16384]
// Output: concat(node_embeds, pos_embeds, neg_embeds) float32 [3*16384*128]
//
// Rounds 3-10 showed rows-in-flight/SM is register-file-bound at ~200 rows
// (per-warp MLP trades 1:1 against occupancy), pinning HBM at ~5.1-5.4 TB/s.
// cp.async (LDGSTS) lands rows in SMEM with ZERO register cost per
// outstanding row, decoupling MLP from occupancy: 8 row slots/warp,
// double-buffered 4-row chunks -> ~8 rows in flight/warp at ~48 warps/SM
// = ~2x the in-flight bytes of any prior version.

#define FULL_MASK 0xFFFFFFFFu
static constexpr int D4            = 32;   // float4s per 128-float row
static constexpr int K             = 32;   // max neighbors
static constexpr int SLOT_ROWS     = 8;    // smem row slots per warp (2 chunks x 4)
static constexpr int WARPS_PER_CTA = 8;
static constexpr int ROW_BYTES     = 512;  // 128 floats

// Issue cp.async for rows [4c, min(4c+4,len)) of this warp's list into
// slots (r & 7), then commit one group (possibly empty — keeps the
// wait_group arithmetic aligned). sbase = this lane's 16B address in slot 0.
__device__ __forceinline__ void issue_chunk(
    uint32_t sbase, const float4* __restrict__ tab, int myidx, int len, int c)
{
    const int r0 = c << 2;
    const int r1 = min(r0 + 4, len);
    for (int r = r0; r < r1; ++r) {
        const int i = __shfl_sync(FULL_MASK, myidx, r);
        const uint32_t dst = sbase + (uint32_t)(r & (SLOT_ROWS - 1)) * ROW_BYTES;
        const void* src = (const void*)(tab + (size_t)i * D4);
        asm volatile("cp.async.cg.shared.global [%0], [%1], 16;"
                     :: "r"(dst), "l"(src));
    }
    asm volatile("cp.async.commit_group;" ::: "memory");
}

__global__ __launch_bounds__(256, 6) void isne_gather_mean_kernel(
    const float4* __restrict__ table,
    const int*    __restrict__ node_idx,
    const int*    __restrict__ pos_idx,
    const int*    __restrict__ pos_len,
    const int*    __restrict__ neg_idx,
    const int*    __restrict__ neg_len,
    float4*       __restrict__ out,
    int B)
{
    __shared__ float4 buf[WARPS_PER_CTA][SLOT_ROWS][32];  // 32 KB

    const int warp  = (int)(threadIdx.x >> 5);
    const int lane  = (int)(threadIdx.x & 31);
    const int gwarp = (int)(blockIdx.x * (blockDim.x >> 5)) + warp;
    if (gwarp >= 3 * B) return;

    int task, b;
    if (gwarp < B)            { task = 0; b = gwarp;         }
    else if (gwarp < 2 * B)   { task = 1; b = gwarp - B;     }
    else                      { task = 2; b = gwarp - 2 * B; }

    const float4* __restrict__ tab = table + lane;  // lane-offset base

    if (task == 0) {
        const int idx = __ldg(&node_idx[b]);
        __stcs(&out[(size_t)b * D4 + lane], __ldg(&tab[(size_t)idx * D4]));
        return;
    }

    const int* __restrict__ idxs = (task == 1) ? pos_idx : neg_idx;
    const int* __restrict__ lens = (task == 1) ? pos_len : neg_len;

    const int len   = __ldg(&lens[b]);
    const int myidx = __ldg(&idxs[(size_t)b * K + lane]);  // lane k holds idx[k]

    const uint32_t sbase =
        (uint32_t)__cvta_generic_to_shared(&buf[warp][0][lane]);

    float4 acc = make_float4(0.f, 0.f, 0.f, 0.f);

    const int nc = (len + 3) >> 2;  // number of 4-row chunks

    // Prologue: two chunks in flight.
    issue_chunk(sbase, tab, myidx, len, 0);
    issue_chunk(sbase, tab, myidx, len, 1);

    for (int c = 0; c < nc; ++c) {
        // Wait until only the most recent group is pending -> chunk c landed.
        asm volatile("cp.async.wait_group 1;" ::: "memory");
        const int r0 = c << 2;
        const int r1 = min(r0 + 4, len);
        #pragma unroll 4
        for (int r = r0; r < r1; ++r) {
            const float4 v = buf[warp][r & (SLOT_ROWS - 1)][lane];
            acc.x += v.x; acc.y += v.y; acc.z += v.z; acc.w += v.w;
        }
        // Refill the slots chunk c just vacated.
        issue_chunk(sbase, tab, myidx, len, c + 2);
    }

    const float scale = (len > 0) ? (1.0f / (float)len) : 0.0f;
    acc.x *= scale; acc.y *= scale; acc.z *= scale; acc.w *= scale;

    __stcs(&out[((size_t)task * B + b) * D4 + lane], acc);
}

extern "C" void kernel_launch(void* const* d_in, const int* in_sizes, int n_in,
                              void* d_out, int out_size)
{
    const float4* table = (const float4*)d_in[0];
    const int*    nidx  = (const int*)d_in[1];
    const int*    pidx  = (const int*)d_in[2];
    const int*    plen  = (const int*)d_in[3];
    const int*    gidx  = (const int*)d_in[4];
    const int*    glen  = (const int*)d_in[5];
    float4*       out   = (float4*)d_out;

    const int B = in_sizes[1];  // 16384

    const int total_warps = 3 * B;  // one warp per output row
    const int threads = 32 * WARPS_PER_CTA;  // 256
    const int blocks  = (total_warps + WARPS_PER_CTA - 1) / WARPS_PER_CTA;

    isne_gather_mean_kernel<<<blocks, threads>>>(
        table, nidx, pidx, plen, gidx, glen, out, B);
}

// round 17
// speedup vs baseline: 1.1297x; 1.0228x over previous
#include <cuda_runtime.h>
#include <cstdint>

// ISNE embedding gather + masked-mean — cp.async pipeline, 128-thread CTAs.
// Inputs (metadata order):
//   d_in[0] node_parameters  float32 [1000000, 128]
//   d_in[1] node_indices     int32   [16384]
//   d_in[2] pos_idx          int32   [16384, 32]
//   d_in[3] pos_len          int32   [16384]
//   d_in[4] neg_idx          int32   [16384, 32]
//   d_in[5] neg_len          int32   [16384]
// Output: concat(node_embeds, pos_embeds, neg_embeds) float32 [3*16384*128]
//
// Established across R3-R13: this is a random-512B-gather problem pinned
// near a ~5.5 TB/s DRAM wall; latency is fully covered (in-flight bytes
// >> BW*latency). This round raises eligible-warp count for the consume
// phases: 4 warps/CTA -> 16KB smem/CTA -> ~13 CTAs/SM = 52 warps (~80% occ)
// vs 49% before, with the same 8-slot double-buffered cp.async pipeline.

#define FULL_MASK 0xFFFFFFFFu
static constexpr int D4            = 32;   // float4s per 128-float row
static constexpr int K             = 32;   // max neighbors
static constexpr int SLOT_ROWS     = 8;    // smem row slots per warp (2 chunks x 4)
static constexpr int WARPS_PER_CTA = 4;
static constexpr int ROW_BYTES     = 512;  // 128 floats

// Issue cp.async for rows [4c, min(4c+4,len)) of this warp's list into
// slots (r & 7), then commit one group (possibly empty — keeps the
// wait_group arithmetic aligned). sbase = this lane's 16B address in slot 0.
__device__ __forceinline__ void issue_chunk(
    uint32_t sbase, const float4* __restrict__ tab, int myidx, int len, int c)
{
    const int r0 = c << 2;
    const int r1 = min(r0 + 4, len);
    for (int r = r0; r < r1; ++r) {
        const int i = __shfl_sync(FULL_MASK, myidx, r);
        const uint32_t dst = sbase + (uint32_t)(r & (SLOT_ROWS - 1)) * ROW_BYTES;
        const void* src = (const void*)(tab + (size_t)i * D4);
        asm volatile("cp.async.cg.shared.global [%0], [%1], 16;"
                     :: "r"(dst), "l"(src));
    }
    asm volatile("cp.async.commit_group;" ::: "memory");
}

__global__ __launch_bounds__(128) void isne_gather_mean_kernel(
    const float4* __restrict__ table,
    const int*    __restrict__ node_idx,
    const int*    __restrict__ pos_idx,
    const int*    __restrict__ pos_len,
    const int*    __restrict__ neg_idx,
    const int*    __restrict__ neg_len,
    float4*       __restrict__ out,
    int B)
{
    __shared__ float4 buf[WARPS_PER_CTA][SLOT_ROWS][32];  // 16 KB

    const int warp  = (int)(threadIdx.x >> 5);
    const int lane  = (int)(threadIdx.x & 31);
    const int gwarp = (int)(blockIdx.x * WARPS_PER_CTA) + warp;
    if (gwarp >= 3 * B) return;

    int task, b;
    if (gwarp < B)            { task = 0; b = gwarp;         }
    else if (gwarp < 2 * B)   { task = 1; b = gwarp - B;     }
    else                      { task = 2; b = gwarp - 2 * B; }

    const float4* __restrict__ tab = table + lane;  // lane-offset base

    if (task == 0) {
        const int idx = __ldg(&node_idx[b]);
        __stcs(&out[(size_t)b * D4 + lane], __ldg(&tab[(size_t)idx * D4]));
        return;
    }

    const int* __restrict__ idxs = (task == 1) ? pos_idx : neg_idx;
    const int* __restrict__ lens = (task == 1) ? pos_len : neg_len;

    const int len   = __ldg(&lens[b]);
    const int myidx = __ldg(&idxs[(size_t)b * K + lane]);  // lane k holds idx[k]

    const uint32_t sbase =
        (uint32_t)__cvta_generic_to_shared(&buf[warp][0][lane]);

    float4 acc = make_float4(0.f, 0.f, 0.f, 0.f);

    const int nc = (len + 3) >> 2;  // number of 4-row chunks

    // Prologue: two chunks in flight.
    issue_chunk(sbase, tab, myidx, len, 0);
    issue_chunk(sbase, tab, myidx, len, 1);

    for (int c = 0; c < nc; ++c) {
        // Wait until only the most recent group is pending -> chunk c landed.
        asm volatile("cp.async.wait_group 1;" ::: "memory");
        const int r0 = c << 2;
        const int r1 = min(r0 + 4, len);
        #pragma unroll 4
        for (int r = r0; r < r1; ++r) {
            const float4 v = buf[warp][r & (SLOT_ROWS - 1)][lane];
            acc.x += v.x; acc.y += v.y; acc.z += v.z; acc.w += v.w;
        }
        // Refill the slots chunk c just vacated.
        issue_chunk(sbase, tab, myidx, len, c + 2);
    }

    const float scale = (len > 0) ? (1.0f / (float)len) : 0.0f;
    acc.x *= scale; acc.y *= scale; acc.z *= scale; acc.w *= scale;

    __stcs(&out[((size_t)task * B + b) * D4 + lane], acc);
}

extern "C" void kernel_launch(void* const* d_in, const int* in_sizes, int n_in,
                              void* d_out, int out_size)
{
    const float4* table = (const float4*)d_in[0];
    const int*    nidx  = (const int*)d_in[1];
    const int*    pidx  = (const int*)d_in[2];
    const int*    plen  = (const int*)d_in[3];
    const int*    gidx  = (const int*)d_in[4];
    const int*    glen  = (const int*)d_in[5];
    float4*       out   = (float4*)d_out;

    const int B = in_sizes[1];  // 16384

    const int total_warps = 3 * B;  // one warp per output row
    const int threads = 32 * WARPS_PER_CTA;  // 128
    const int blocks  = (total_warps + WARPS_PER_CTA - 1) / WARPS_PER_CTA;

    isne_gather_mean_kernel<<<blocks, threads>>>(
        table, nidx, pidx, plen, gidx, glen, out, B);
}